// round 4
// baseline (speedup 1.0000x reference)
#include <cuda_runtime.h>
#include <math.h>

#define NLOC 50000
#define BB 4
#define TT 16
#define NFEAT 4
#define NTOT (BB*NLOC)   /* 200000 */
#define H 32
#define FULL 0xffffffffu

// Scratch (no allocation allowed):
__device__ float g_z[(size_t)NTOT*H];   // node features after linear (zs source)
__device__ float g_h[(size_t)NTOT*H];   // aggregation target
__device__ float g_s[NTOT];             // per-node attention src-term
__device__ float g_d[NTOT];             // per-node attention dst-term

__device__ __forceinline__ float warp_sum(float v){
  #pragma unroll
  for(int o=16;o;o>>=1) v += __shfl_xor_sync(FULL, v, o);
  return v;
}
__device__ __forceinline__ float sigm(float x){ return 1.f/(1.f+expf(-x)); }
__device__ __forceinline__ float eluf(float x){ return x>0.f ? x : expm1f(x); }

// ---------------- Layer-1 node kernel: z1 = fc1(Xf), s/d attention scalars ----
__global__ void k_node1(const float* __restrict__ X,
                        const float* __restrict__ W,    // (32,64) row-major
                        const float* __restrict__ bvec, // (32)
                        const float* __restrict__ aW)   // (64)
{
  __shared__ float Ws[64*32];   // transposed [j][k]
  __shared__ float aWs[64];
  __shared__ float bs[32];
  int tid = threadIdx.x;
  for(int i=tid;i<64*32;i+=256){ int k=i>>6, j=i&63; Ws[j*32+k]=W[i]; }
  if(tid<64) aWs[tid]=aW[tid];
  if(tid<32) bs[tid]=bvec[tid];
  __syncthreads();
  int lane=tid&31, wid=tid>>5;
  int n = blockIdx.x*8 + wid;
  if(n>=NTOT) return;
  int b=n/NLOC, loc=n-b*NLOC;
  // Xf[n, j] = X[b, j>>2, loc, j&3]
  const float* Xb = X + ((size_t)b*TT*NLOC + loc)*NFEAT;
  int j1 = lane+32;
  float x0 = Xb[(size_t)(lane>>2)*NLOC*NFEAT + (lane&3)];
  float x1 = Xb[(size_t)(j1  >>2)*NLOC*NFEAT + (j1  &3)];
  float z = bs[lane];
  #pragma unroll
  for(int j=0;j<32;j++) z = fmaf(Ws[j*32+lane],      __shfl_sync(FULL,x0,j), z);
  #pragma unroll
  for(int j=0;j<32;j++) z = fmaf(Ws[(j+32)*32+lane], __shfl_sync(FULL,x1,j), z);
  float sv = warp_sum(z*aWs[lane]);
  float dv = warp_sum(z*aWs[32+lane]);
  g_z[(size_t)n*H+lane] = z;
  g_h[(size_t)n*H+lane] = 0.f;
  if(lane==0){ g_s[n]=sv; g_d[n]=dv; }
}

// ---------------- Edge scatter: h[dst] += z[src] * lrelu(s[src]+d[dst]+ab) ----
__global__ void k_edge(const int* __restrict__ adj, int E,
                       const float* __restrict__ att_b)
{
  int e = blockIdx.x*8 + (threadIdx.x>>5);
  if(e>=E) return;
  int lane = threadIdx.x&31;
  int src = __ldg(&adj[e]);
  int dst = __ldg(&adj[E+e]);
  float ev = g_s[src] + g_d[dst] + __ldg(att_b);
  ev = ev>=0.f ? ev : 0.01f*ev;
  float v = g_z[(size_t)src*H + lane] * ev;
  atomicAdd(&g_h[(size_t)dst*H + lane], v);
}

// ---------------- Layer-2 node kernel: z2 = fc2(elu(h1)), new s/d -------------
__global__ void k_node2(const float* __restrict__ W,    // (32,32)
                        const float* __restrict__ bvec,
                        const float* __restrict__ aW)   // (64)
{
  __shared__ float Ws[32*32];
  __shared__ float aWs[64];
  __shared__ float bs[32];
  int tid=threadIdx.x;
  for(int i=tid;i<32*32;i+=256){ int k=i>>5, j=i&31; Ws[j*32+k]=W[i]; }
  if(tid<64) aWs[tid]=aW[tid];
  if(tid<32) bs[tid]=bvec[tid];
  __syncthreads();
  int lane=tid&31, wid=tid>>5;
  int n = blockIdx.x*8+wid;
  if(n>=NTOT) return;
  float hin = eluf(g_h[(size_t)n*H+lane]);
  float z = bs[lane];
  #pragma unroll
  for(int j=0;j<32;j++) z = fmaf(Ws[j*32+lane], __shfl_sync(FULL,hin,j), z);
  float sv = warp_sum(z*aWs[lane]);
  float dv = warp_sum(z*aWs[32+lane]);
  g_z[(size_t)n*H+lane]=z;
  g_h[(size_t)n*H+lane]=0.f;    // reset for layer-2 aggregation
  if(lane==0){ g_s[n]=sv; g_d[n]=dv; }
}

// ---------------- Final: elu -> GRU(h0=0) -> heads -> SIR rollout -> out ------
__global__ void k_final(const float* __restrict__ X,
                        const float* __restrict__ states,
                        const float* __restrict__ Nvec,
                        const float* __restrict__ Wih,  // (96,32)
                        const float* __restrict__ bih,
                        const float* __restrict__ bhh,
                        const float* __restrict__ WI, const float* __restrict__ bI,
                        const float* __restrict__ WR, const float* __restrict__ bR,
                        const float* __restrict__ Wsir, const float* __restrict__ bsir,
                        float* __restrict__ out)
{
  __shared__ float Wihs[32*96];  // transposed [j][k]
  __shared__ float bihs[96], bhhs[96];
  __shared__ float Wh[18*34];    // rows: 0-7 WI, 8-15 WR, 16-17 Wsir
  __shared__ float bh[18];
  __shared__ float stage[8][32];
  int tid=threadIdx.x;
  for(int i=tid;i<96*32;i+=256){ int k=i>>5, j=i&31; Wihs[j*96+k]=Wih[i]; }
  if(tid<96){ bihs[tid]=bih[tid]; bhhs[tid]=bhh[tid]; }
  for(int i=tid;i<8*34;i+=256){ Wh[i]=WI[i]; Wh[8*34+i]=WR[i]; }
  if(tid<2*34) Wh[16*34+tid]=Wsir[tid];
  if(tid<8) bh[tid]=bI[tid];
  else if(tid<16) bh[tid]=bR[tid-8];
  else if(tid<18) bh[tid]=bsir[tid-16];
  __syncthreads();
  int lane=tid&31, wid=tid>>5;
  int n = blockIdx.x*8+wid;
  if(n>=NTOT) return;
  float h2 = eluf(g_h[(size_t)n*H+lane]);
  float gi0=bihs[lane], gi1=bihs[32+lane], gi2=bihs[64+lane];
  #pragma unroll
  for(int j=0;j<32;j++){
    float hv=__shfl_sync(FULL,h2,j);
    gi0=fmaf(Wihs[j*96+lane],    hv,gi0);
    gi1=fmaf(Wihs[j*96+32+lane], hv,gi1);
    gi2=fmaf(Wihs[j*96+64+lane], hv,gi2);
  }
  float r  = sigm(gi0 + bhhs[lane]);
  float zg = sigm(gi1 + bhhs[32+lane]);
  float nn = tanhf(gi2 + r*bhhs[64+lane]);
  float hout = (1.f-zg)*nn;

  int b=n/NLOC, loc=n-b*NLOC;
  const float* Xl = X + ((size_t)(b*TT+TT-1)*NLOC + loc)*NFEAT;
  float ldI = Xl[1], ldR = Xl[2];

  // 18 head rows in parallel across lanes (lane<18), hc = [hout(32), ldI, ldR]
  float acc = lane<18 ? bh[lane] : 0.f;
  #pragma unroll
  for(int j=0;j<32;j++){
    float hv=__shfl_sync(FULL,hout,j);
    if(lane<18) acc = fmaf(Wh[lane*34+j],hv,acc);
  }
  if(lane<18) acc = fmaf(Wh[lane*34+32],ldI, fmaf(Wh[lane*34+33],ldR,acc));
  float alpha = sigm(__shfl_sync(FULL, acc, 16));
  float beta  = sigm(__shfl_sync(FULL, acc, 17));

  if(lane<8)        stage[wid][2*lane]       = acc;   // pred_I[h]
  else if(lane<16)  stage[wid][2*(lane-8)+1] = acc;   // pred_R[h]

  // SIR rollout (all lanes redundantly; designated lanes stage dI/dR)
  float I  = states[(size_t)n*2];
  float Rr = states[(size_t)n*2+1];
  float Nv = Nvec[loc];
  #pragma unroll
  for(int hh=0;hh<8;hh++){
    float S  = Nv - I - Rr;
    float dI = alpha*I*(S/Nv) - beta*I;
    float dR = beta*I;
    if(lane==16+2*hh) stage[wid][lane]=dI;
    if(lane==17+2*hh) stage[wid][lane]=dR;
    I += dI; Rr += dR;
  }
  __syncwarp();
  float v = stage[wid][lane];
  if(lane<16) out[(size_t)n*16+lane]=v;                               // pred (ntot,8,2)
  else        out[(size_t)NTOT*16 + (size_t)n*16 + (lane-16)]=v;      // phy  (ntot,8,2)
}

extern "C" void kernel_launch(void* const* d_in, const int* in_sizes, int n_in,
                              void* d_out, int out_size)
{
  const float* X      = (const float*)d_in[0];
  const int*   adj    = (const int*)d_in[1];     // JAX int64 request -> int32 in practice
  const float* states = (const float*)d_in[2];
  const float* Nvec   = (const float*)d_in[3];
  const float* fc1_W  = (const float*)d_in[4];
  const float* fc1_b  = (const float*)d_in[5];
  const float* att1_W = (const float*)d_in[6];
  const float* att1_b = (const float*)d_in[7];
  const float* fc2_W  = (const float*)d_in[8];
  const float* fc2_b  = (const float*)d_in[9];
  const float* att2_W = (const float*)d_in[10];
  const float* att2_b = (const float*)d_in[11];
  const float* gru_Wih= (const float*)d_in[12];
  /* d_in[13] = gru_Whh: unused (h0 == 0) */
  const float* gru_bih= (const float*)d_in[14];
  const float* gru_bhh= (const float*)d_in[15];
  const float* WI   = (const float*)d_in[16];
  const float* bI   = (const float*)d_in[17];
  const float* WR   = (const float*)d_in[18];
  const float* bR   = (const float*)d_in[19];
  const float* Wsir = (const float*)d_in[20];
  const float* bsir = (const float*)d_in[21];
  float* out = (float*)d_out;

  int E = in_sizes[1]/2;
  int nodeBlocks = (NTOT+7)/8;
  int edgeBlocks = (E+7)/8;

  k_node1<<<nodeBlocks,256>>>(X, fc1_W, fc1_b, att1_W);
  k_edge <<<edgeBlocks,256>>>(adj, E, att1_b);
  k_node2<<<nodeBlocks,256>>>(fc2_W, fc2_b, att2_W);
  k_edge <<<edgeBlocks,256>>>(adj, E, att2_b);
  k_final<<<nodeBlocks,256>>>(X, states, Nvec, gru_Wih, gru_bih, gru_bhh,
                              WI, bI, WR, bR, Wsir, bsir, out);
}